// round 16
// baseline (speedup 1.0000x reference)
#include <cuda_runtime.h>
#include <math.h>

// Problem dims
#define BB   32
#define TL   256
#define DL   512
#define HH   512
#define VV   2000
#define MM   256
#define G4   2048
#define XD   2512
#define NSTEP 100
#define LDP  2048        // row stride in transposed partial buffers

// Persistent scratch
__device__ float g_x[BB * XD];                 // decoder input [b][k]
__device__ float g_h0[BB * HH], g_c0[BB * HH];
__device__ float g_h1[BB * HH], g_c1[BB * HH];
__device__ float g_ctx[BB * HH];               // context [b][d]
__device__ float g_p0[8 * G4 * BB];            // gates0 partials [s][r][b]
__device__ float g_p1[(size_t)4 * BB * LDP];   // gates1 partials [s][b][r]
__device__ float g_pl[(size_t)4 * BB * LDP];   // logits partials [s][b][v]
__device__ float g_clisT[(size_t)BB * MM * TL];// relu(psi) transposed [b][m][t]

__device__ __forceinline__ float sigmoidf_(float x) { return 1.f / (1.f + expf(-x)); }

// ---------------------------------------------------------------------------
// One-time init
// ---------------------------------------------------------------------------
__global__ void k_init(const float* __restrict__ lis) {
    int i = blockIdx.x * blockDim.x + threadIdx.x;
    if (i < BB * XD) {
        int b = i / XD, k = i % XD;
        float v = 0.f;
        if (k == 0) v = 1.f;
        else if (k >= VV) v = lis[(size_t)b * TL * DL + (k - VV)];
        g_x[i] = v;
    }
    if (i < BB * HH) {
        g_h0[i] = 0.f; g_c0[i] = 0.f; g_h1[i] = 0.f; g_c1[i] = 0.f;
    }
}

// ---------------------------------------------------------------------------
// One-time psi (R2-proven)
// ---------------------------------------------------------------------------
__global__ void k_psi(const float* __restrict__ lis,
                      const float* __restrict__ Wpsi,
                      const float* __restrict__ bpsi) {
    int mb = blockIdx.x, tb = blockIdx.y, b = blockIdx.z;
    int tid = threadIdx.x;
    int mg = tid >> 4, tg = tid & 15;
    __shared__ float Ws[32 * 33];
    __shared__ float Ls[64 * 33];
    float acc[4][4] = {};
    const float* lb = lis + (size_t)b * TL * DL;
    for (int kc = 0; kc < DL; kc += 32) {
#pragma unroll
        for (int i = 0; i < 8; i++) {
            int lin = tid + i * 128;
            int row = lin >> 5, kk = lin & 31;
            Ws[row * 33 + kk] = Wpsi[(size_t)(mb * 32 + row) * DL + kc + kk];
        }
#pragma unroll
        for (int i = 0; i < 16; i++) {
            int lin = tid + i * 128;
            int row = lin >> 5, kk = lin & 31;
            Ls[row * 33 + kk] = lb[(size_t)(tb * 64 + row) * DL + kc + kk];
        }
        __syncthreads();
#pragma unroll 8
        for (int kk = 0; kk < 32; kk++) {
            float wv[4], lv[4];
#pragma unroll
            for (int i = 0; i < 4; i++) wv[i] = Ws[(mg * 4 + i) * 33 + kk];
#pragma unroll
            for (int j = 0; j < 4; j++) lv[j] = Ls[(tg * 4 + j) * 33 + kk];
#pragma unroll
            for (int i = 0; i < 4; i++)
#pragma unroll
                for (int j = 0; j < 4; j++) acc[i][j] = fmaf(wv[i], lv[j], acc[i][j]);
        }
        __syncthreads();
    }
#pragma unroll
    for (int i = 0; i < 4; i++) {
        int m = mb * 32 + mg * 4 + i;
        float bias = bpsi[m];
#pragma unroll
        for (int j = 0; j < 4; j++) {
            int t = tb * 64 + tg * 4 + j;
            g_clisT[((size_t)b * MM + m) * TL + t] = fmaxf(acc[i][j] + bias, 0.f);
        }
    }
}

// ---------------------------------------------------------------------------
// GEMM tile core (R2-proven): 64 rows x 32 batch, 128 threads, 4x4 micro.
// Computes acc[i][j]; caller stores. k indices pair-local; W offset via Wp.
// ---------------------------------------------------------------------------
__device__ __forceinline__ void gemm_core(
        const float* __restrict__ Wp, int ldw, int Mrows,
        const float* __restrict__ Xp, int ldx,
        int rBase, int k0, int k1, float acc[4][4],
        float* Ws, float* Xs) {
    int tid = threadIdx.x;
    int rowg = tid >> 3, bg = tid & 7;
    for (int kc = k0; kc < k1; kc += 32) {
#pragma unroll
        for (int i = 0; i < 16; i++) {          // W tile: 64 rows x 32 k
            int lin = tid + i * 128;
            int row = lin >> 5, kk = lin & 31;
            int k = kc + kk;
            int r = rBase + row;
            float v = 0.f;
            if (k < k1 && r < Mrows) v = Wp[(size_t)r * ldw + k];
            Ws[row * 33 + kk] = v;
        }
#pragma unroll
        for (int i = 0; i < 8; i++) {           // X tile: 32 b x 32 k
            int lin = tid + i * 128;
            int bb = lin >> 5, kk = lin & 31;
            int k = kc + kk;
            Xs[bb * 33 + kk] = (k < k1) ? Xp[(size_t)bb * ldx + k] : 0.f;
        }
        __syncthreads();
#pragma unroll 8
        for (int kk = 0; kk < 32; kk++) {
            float wv[4], xv[4];
#pragma unroll
            for (int i = 0; i < 4; i++) wv[i] = Ws[(rowg * 4 + i) * 33 + kk];
#pragma unroll
            for (int j = 0; j < 4; j++) xv[j] = Xs[(bg * 4 + j) * 33 + kk];
#pragma unroll
            for (int i = 0; i < 4; i++)
#pragma unroll
                for (int j = 0; j < 4; j++) acc[i][j] = fmaf(wv[i], xv[j], acc[i][j]);
        }
        __syncthreads();
    }
}

// Node 1: gates0 partials, output [s][r][b] (R2 layout). grid (32, 8).
// y<6: Wih0 (chunk 419); y 6,7: Whh0 (chunk 256).
__global__ void __launch_bounds__(128) k_g0(
        const float* __restrict__ Wih0, const float* __restrict__ Whh0) {
    __shared__ float Ws[64 * 33];
    __shared__ float Xs[32 * 33];
    int s = blockIdx.y, rBase = blockIdx.x * 64;
    float acc[4][4] = {};
    if (s < 6) {
        int k0 = s * 419, k1 = min(XD, k0 + 419);
        gemm_core(Wih0, XD, G4, g_x, XD, rBase, k0, k1, acc, Ws, Xs);
    } else {
        int sl = s - 6;
        gemm_core(Whh0, HH, G4, g_h0, HH, rBase, sl * 256, sl * 256 + 256, acc, Ws, Xs);
    }
    int rowg = threadIdx.x >> 3, bg = threadIdx.x & 7;
    float* Pout = g_p0 + (size_t)s * G4 * BB;
#pragma unroll
    for (int i = 0; i < 4; i++) {
        int r = rBase + rowg * 4 + i;
#pragma unroll
        for (int j = 0; j < 4; j++)
            Pout[(size_t)r * BB + bg * 4 + j] = acc[i][j];
    }
}

// Node 3: gates1 partials, output TRANSPOSED [s][b][r]. grid (32, 4).
// y 0,1: Wih1 @ h0; y 2,3: Whh1 @ h1_prev. chunk 256.
__global__ void __launch_bounds__(128) k_g1(
        const float* __restrict__ Wih1, const float* __restrict__ Whh1) {
    __shared__ float Ws[64 * 33];
    __shared__ float Xs[32 * 33];
    int s = blockIdx.y, rBase = blockIdx.x * 64;
    float acc[4][4] = {};
    if (s < 2) {
        gemm_core(Wih1, HH, G4, g_h0, HH, rBase, s * 256, s * 256 + 256, acc, Ws, Xs);
    } else {
        int sl = s - 2;
        gemm_core(Whh1, HH, G4, g_h1, HH, rBase, sl * 256, sl * 256 + 256, acc, Ws, Xs);
    }
    int rowg = threadIdx.x >> 3, bg = threadIdx.x & 7;
    float* Pout = g_p1 + (size_t)s * BB * LDP;
#pragma unroll
    for (int i = 0; i < 4; i++) {
        int r = rBase + rowg * 4 + i;
#pragma unroll
        for (int j = 0; j < 4; j++)
            Pout[(size_t)(bg * 4 + j) * LDP + r] = acc[i][j];
    }
}

// Node 5: logits partials, output TRANSPOSED [s][b][v]. grid (32, 4).
// y 0,1: Wc[:, :512] @ h1; y 2,3: Wc[:, 512:] @ ctx. chunk 256, ldw=1024.
__global__ void __launch_bounds__(128) k_glog(const float* __restrict__ Wc) {
    __shared__ float Ws[64 * 33];
    __shared__ float Xs[32 * 33];
    int s = blockIdx.y, rBase = blockIdx.x * 64;
    float acc[4][4] = {};
    if (s < 2) {
        gemm_core(Wc, 2 * HH, VV, g_h1, HH, rBase, s * 256, s * 256 + 256, acc, Ws, Xs);
    } else {
        int sl = s - 2;
        gemm_core(Wc + HH, 2 * HH, VV, g_ctx, HH, rBase, sl * 256, sl * 256 + 256, acc, Ws, Xs);
    }
    int rowg = threadIdx.x >> 3, bg = threadIdx.x & 7;
    float* Pout = g_pl + (size_t)s * BB * LDP;
#pragma unroll
    for (int i = 0; i < 4; i++) {
        int r = rBase + rowg * 4 + i;
        if (r < VV)
#pragma unroll
            for (int j = 0; j < 4; j++)
                Pout[(size_t)(bg * 4 + j) * LDP + r] = acc[i][j];
    }
}

// ---------------------------------------------------------------------------
// Node 2: LSTM cell 0, templated slot count (unrolled reduce). 64 blocks.
// Partials [s][r][b]: coalesced over b (idx & 31).
// ---------------------------------------------------------------------------
template <int NS>
__global__ void __launch_bounds__(256) k_cell(
        const float* __restrict__ P,
        const float* __restrict__ bih, const float* __restrict__ bhh,
        float* __restrict__ hbuf, float* __restrict__ cbuf) {
    int idx = blockIdx.x * 256 + threadIdx.x;
    if (idx >= BB * HH) return;
    int b = idx & 31, j = idx >> 5;
    float g[4];
#pragma unroll
    for (int gi = 0; gi < 4; gi++) {
        int r = gi * HH + j;
        float v = bih[r] + bhh[r];
        const float* p = P + (size_t)r * BB + b;
#pragma unroll
        for (int s = 0; s < NS; s++) v += p[(size_t)s * G4 * BB];
        g[gi] = v;
    }
    float ig = sigmoidf_(g[0]);
    float fg = sigmoidf_(g[1]);
    float gg = tanhf(g[2]);
    float og = sigmoidf_(g[3]);
    float cn = fg * cbuf[b * HH + j] + ig * gg;
    float hn = og * tanhf(cn);
    cbuf[b * HH + j] = cn;
    hbuf[b * HH + j] = hn;
}

// ---------------------------------------------------------------------------
// Node 4: FUSED cell1 + attention. One block per batch, 256 threads.
// cell1 from [s][b][r] partials (coalesced over r) -> h1 in smem ->
// phi -> energy -> softmax -> context. Writes h1, c1, attn, ctx, x-feedback.
// ---------------------------------------------------------------------------
__global__ void __launch_bounds__(256) k_cellattn(
        const float* __restrict__ bih1, const float* __restrict__ bhh1,
        const float* __restrict__ lis,
        const float* __restrict__ Wphi, const float* __restrict__ bphi,
        float* __restrict__ attn_out) {
    __shared__ float h1s[HH];
    __shared__ float cd[MM];
    __shared__ float av[TL];
    __shared__ float rbuf[TL];
    int b = blockIdx.x, tid = threadIdx.x;
    const float* Pb = g_p1 + (size_t)b * LDP;

    // ---- cell1: thread handles j = tid, tid+256 ----
#pragma unroll
    for (int half = 0; half < 2; half++) {
        int j = tid + half * 256;
        float g[4];
#pragma unroll
        for (int gi = 0; gi < 4; gi++) {
            int r = gi * HH + j;
            float v = bih1[r] + bhh1[r];
#pragma unroll
            for (int s = 0; s < 4; s++) v += Pb[(size_t)s * BB * LDP + r];
            g[gi] = v;
        }
        float ig = sigmoidf_(g[0]);
        float fg = sigmoidf_(g[1]);
        float gg = tanhf(g[2]);
        float og = sigmoidf_(g[3]);
        float cn = fg * g_c1[b * HH + j] + ig * gg;
        float hn = og * tanhf(cn);
        g_c1[b * HH + j] = cn;
        g_h1[b * HH + j] = hn;
        h1s[j] = hn;
    }
    __syncthreads();

    // ---- phi: warp-per-m GEMV (validated R9/R12/R14/R15) ----
    int warp = tid >> 5, lane = tid & 31;
    for (int m = warp; m < MM; m += 8) {
        const float* w = Wphi + (size_t)m * HH;
        float p = 0.f;
#pragma unroll 4
        for (int k = lane; k < HH; k += 32) p = fmaf(w[k], h1s[k], p);
#pragma unroll
        for (int o = 16; o; o >>= 1) p += __shfl_down_sync(0xffffffffu, p, o);
        if (lane == 0) cd[m] = fmaxf(p + bphi[m], 0.f);
    }
    __syncthreads();

    // ---- energy / softmax / context ----
    const float* cl = g_clisT + (size_t)b * MM * TL + tid;
    float e = 0.f;
#pragma unroll 8
    for (int m = 0; m < MM; m++) e = fmaf(cd[m], cl[(size_t)m * TL], e);
    rbuf[tid] = e; __syncthreads();
    for (int o = 128; o > 0; o >>= 1) {
        if (tid < o) rbuf[tid] = fmaxf(rbuf[tid], rbuf[tid + o]);
        __syncthreads();
    }
    float mx = rbuf[0]; __syncthreads();
    float p = expf(e - mx);
    rbuf[tid] = p; __syncthreads();
    for (int o = 128; o > 0; o >>= 1) {
        if (tid < o) rbuf[tid] += rbuf[tid + o];
        __syncthreads();
    }
    float a = p / rbuf[0];
    av[tid] = a;
    attn_out[(size_t)b * TL + tid] = a;
    __syncthreads();
    const float* lb = lis + (size_t)b * TL * DL;
#pragma unroll
    for (int dd = 0; dd < 2; dd++) {
        int d = tid + dd * 256;
        float cx = 0.f;
#pragma unroll 4
        for (int t = 0; t < TL; t++) cx = fmaf(av[t], lb[(size_t)t * DL + d], cx);
        g_ctx[(size_t)b * HH + d] = cx;
        g_x[(size_t)b * XD + VV + d] = cx;
    }
}

// ---------------------------------------------------------------------------
// Node 6: log-softmax + feedback. [s][b][v] partials: coalesced over v.
// ---------------------------------------------------------------------------
__global__ void __launch_bounds__(256) k_lsm(
        const float* __restrict__ bc, float* __restrict__ preds_out) {
    __shared__ float lg[VV];
    __shared__ float rbuf[256];
    int b = blockIdx.x, tid = threadIdx.x;
    const float* Pb = g_pl + (size_t)b * LDP;
    float lmax = -1e30f;
    for (int v = tid; v < VV; v += 256) {
        float x = bc[v];
#pragma unroll
        for (int s = 0; s < 4; s++) x += Pb[(size_t)s * BB * LDP + v];
        lg[v] = x;
        lmax = fmaxf(lmax, x);
    }
    rbuf[tid] = lmax; __syncthreads();
    for (int o = 128; o > 0; o >>= 1) {
        if (tid < o) rbuf[tid] = fmaxf(rbuf[tid], rbuf[tid + o]);
        __syncthreads();
    }
    float mx = rbuf[0]; __syncthreads();
    float ls = 0.f;
    for (int v = tid; v < VV; v += 256) ls += expf(lg[v] - mx);
    rbuf[tid] = ls; __syncthreads();
    for (int o = 128; o > 0; o >>= 1) {
        if (tid < o) rbuf[tid] += rbuf[tid + o];
        __syncthreads();
    }
    float lse = mx + logf(rbuf[0]);
    for (int v = tid; v < VV; v += 256) {
        float r = lg[v] - lse;
        preds_out[(size_t)b * VV + v] = r;
        g_x[(size_t)b * XD + v] = r;
    }
}

// ---------------------------------------------------------------------------
// Launcher: 6 nodes/step, single stream, graph-capturable, allocation-free.
// ---------------------------------------------------------------------------
extern "C" void kernel_launch(void* const* d_in, const int* in_sizes, int n_in,
                              void* d_out, int out_size) {
    const float* lis  = (const float*)d_in[0];
    const float* Wih0 = (const float*)d_in[1];
    const float* Whh0 = (const float*)d_in[2];
    const float* bih0 = (const float*)d_in[3];
    const float* bhh0 = (const float*)d_in[4];
    const float* Wih1 = (const float*)d_in[5];
    const float* Whh1 = (const float*)d_in[6];
    const float* bih1 = (const float*)d_in[7];
    const float* bhh1 = (const float*)d_in[8];
    const float* Wphi = (const float*)d_in[9];
    const float* bphi = (const float*)d_in[10];
    const float* Wpsi = (const float*)d_in[11];
    const float* bpsi = (const float*)d_in[12];
    const float* Wc   = (const float*)d_in[13];
    const float* bc   = (const float*)d_in[14];

    float* preds = (float*)d_out;                      // [100,32,2000]
    float* attns = preds + (size_t)NSTEP * BB * VV;    // [100,32,256]

    float *p0, *h0, *c0;
    cudaGetSymbolAddress((void**)&p0, g_p0);
    cudaGetSymbolAddress((void**)&h0, g_h0);
    cudaGetSymbolAddress((void**)&c0, g_c0);

    k_init<<<(BB * XD + 255) / 256, 256>>>(lis);
    k_psi<<<dim3(8, 4, BB), 128>>>(lis, Wpsi, bpsi);

    for (int t = 0; t < NSTEP; t++) {
        // 1: gates0 partials (Wih0@x 6 slots + Whh0@h0 2 slots)
        k_g0<<<dim3(32, 8), 128>>>(Wih0, Whh0);
        // 2: cell0 (unrolled 8-slot reduce)
        k_cell<8><<<64, 256>>>(p0, bih0, bhh0, h0, c0);
        // 3: gates1 partials (Wih1@h0 + Whh1@h1_prev), transposed out
        k_g1<<<dim3(32, 4), 128>>>(Wih1, Whh1);
        // 4: fused cell1 + phi + attention
        k_cellattn<<<32, 256>>>(bih1, bhh1, lis, Wphi, bphi,
                                attns + (size_t)t * BB * TL);
        // 5: logits partials (h1-half + ctx-half), transposed out
        k_glog<<<dim3(32, 4), 128>>>(Wc);
        // 6: log-softmax + feedback
        k_lsm<<<32, 256>>>(bc, preds + (size_t)t * BB * VV);
    }
}